// round 8
// baseline (speedup 1.0000x reference)
#include <cuda_runtime.h>
#include <cuda_fp16.h>

#define NN 50000
#define EE 1250000
#define HALF 625000
#define HH 64
#define BB 500
#define BN_EPS 1e-5f

#define NB2 32768
#define XLO (-8.0f)
#define INVH2 2048.0f          // NB2/16
#define H2 4.8828125e-4f       // 16/NB2

// ---------------- device scratch ----------------
__device__ float   g_T[(long)NB2 * HH];    // 8MB fp32 table (pre-affine, for stats)
__device__ __half2 g_Th[(long)NB2 * 32];   // 4MB fp16 table, BN2 affine folded
__device__ __half2 g_emh[100 * 32];        // fp16 edge_emb
__device__ __half2 g_ea[(long)EE * 32];    // 160MB precomputed ea (fp16), layer-invariant
__device__ int     g_sd[EE];               // src|dst<<16
__device__ int     g_bt[EE];               // ty|bin<<7
__device__ int     g_cnt[NB2];
__device__ float   g_h[NN * HH];
__device__ float   g_agg[NN * HH];
__device__ float   g_hg[BB * HH];
__device__ float   g_y1[NN * 64];
__device__ float   g_y2[NN * 32];
__device__ float   g_red[22592];
__device__ float   g_coef[1024];

#define OFF_X   0
#define OFF_D2  64
#define OFF_C1  4160
#define OFF_C2  8256
#define OFF_C3  12352
#define OFF_O1  16448
#define OFF_O2  20544

__device__ __forceinline__ float sp(float x) {
    float t, l;
    asm("ex2.approx.ftz.f32 %0, %1;" : "=f"(t) : "f"(x * 1.44269504f));
    asm("lg2.approx.f32 %0, %1;" : "=f"(l) : "f"(1.0f + t));
    float r = l * 0.69314718f;
    return x > 20.0f ? x : r;
}

// ---------------- setup kernels ----------------

__global__ void kzero() {
    int i = blockIdx.x * 256 + threadIdx.x;
    if (i < 22592) g_red[i] = 0.0f;
    if (i < BB * HH) g_hg[i] = 0.0f;
    if (i < NB2) g_cnt[i] = 0;
}

// one pass over edges: pack records, count bin, x stats
__global__ void kprep(const int* __restrict__ ei, const int* __restrict__ et,
                      const float* __restrict__ x) {
    int e = blockIdx.x * 256 + threadIdx.x;
    float sx = 0.f, sxx = 0.f;
    if (e < EE) {
        float xv = x[e];
        sx = xv; sxx = xv * xv;
        float u = (xv - XLO) * INVH2;
        int b = (int)u;
        b = max(0, min(NB2 - 1, b));
        atomicAdd(&g_cnt[b], 1);
        g_sd[e] = ei[e] | (ei[EE + e] << 16);
        g_bt[e] = et[e] | (b << 7);
    }
    __shared__ float ss[256], sq[256];
    int t = threadIdx.x;
    ss[t] = sx; sq[t] = sxx;
    __syncthreads();
    for (int o = 128; o > 0; o >>= 1) {
        if (t < o) { ss[t] += ss[t + o]; sq[t] += sq[t + o]; }
        __syncthreads();
    }
    if (t == 0) {
        int r = blockIdx.x & 31;
        atomicAdd(&g_red[OFF_X + 2 * r], ss[0]);
        atomicAdd(&g_red[OFF_X + 2 * r + 1], sq[0]);
    }
}

__global__ void kfin_d1(const float* __restrict__ w_d1, const float* __restrict__ g_d1,
                        const float* __restrict__ be_d1) {
    __shared__ float S[2];
    if (threadIdx.x == 0) {
        float s = 0.f, q = 0.f;
        for (int r = 0; r < 32; r++) { s += g_red[2 * r]; q += g_red[2 * r + 1]; }
        S[0] = s; S[1] = q;
    }
    __syncthreads();
    float mx = S[0] / (float)EE;
    float vx = S[1] / (float)EE - mx * mx;
    int h = threadIdx.x;
    float w = w_d1[h];
    float a = w * rsqrtf(vx * w * w + BN_EPS) * g_d1[h];
    g_coef[h] = a;
    g_coef[64 + h] = -mx * a + be_d1[h];
}

// table build: tiled GEMM, block = 64 bins x 64 k
__global__ void ktable(const float* __restrict__ w_d2) {
    __shared__ float w2s[64 * 68];
    __shared__ float spv[64 * 64];
    int t = threadIdx.x;
    int j0 = blockIdx.x * 64;

    for (int i = t * 4; i < 4096; i += 1024) {
        float4 v = __ldg((const float4*)&w_d2[i]);
        int k = i >> 6, f = i & 63;
        *(float4*)&w2s[k * 68 + f] = v;
    }
    {
        int f = t & 63;
        float a = g_coef[f], c = g_coef[64 + f];
        for (int j = t >> 6; j < 64; j += 4) {
            float xj = XLO + ((float)(j0 + j) + 0.5f) * H2;
            spv[j * 64 + f] = sp(a * xj + c);
        }
    }
    __syncthreads();

    int k = t & 63;
    int jg = (t >> 6) * 16;
    float acc[16];
#pragma unroll
    for (int i = 0; i < 16; i++) acc[i] = 0.f;
    for (int f4 = 0; f4 < 64; f4 += 4) {
        float4 w4 = *(const float4*)&w2s[k * 68 + f4];
#pragma unroll
        for (int i = 0; i < 16; i++) {
            float4 d = *(const float4*)&spv[(jg + i) * 64 + f4];
            acc[i] += d.x * w4.x + d.y * w4.y + d.z * w4.z + d.w * w4.w;
        }
    }
#pragma unroll
    for (int i = 0; i < 16; i++)
        g_T[(long)(j0 + jg + i) * 64 + k] = acc[i];
}

// BN2 stats from counts (exact for nearest-neighbor quantized d2)
__global__ void kd2stat() {
    int k = threadIdx.x;
    int b0 = blockIdx.x * 64;
    float s = 0.f, q = 0.f;
    for (int j = 0; j < 64; j++) {
        float c = (float)g_cnt[b0 + j];
        float tv = g_T[(long)(b0 + j) * 64 + k];
        s += c * tv;
        q += c * tv * tv;
    }
    int r = blockIdx.x & 31;
    atomicAdd(&g_red[OFF_D2 + r * 128 + k], s);
    atomicAdd(&g_red[OFF_D2 + r * 128 + 64 + k], q);
}

__global__ void kfinbn(int redoff, int F, float cnt, const float* __restrict__ g,
                       const float* __restrict__ be, int coefoff) {
    int k = threadIdx.x;
    if (k >= F) return;
    float s = 0.f, q = 0.f;
    for (int r = 0; r < 32; r++) {
        s += g_red[redoff + r * 2 * F + k];
        q += g_red[redoff + r * 2 * F + F + k];
    }
    float m = s / cnt;
    float v = q / cnt - m * m;
    float sc = g[k] * rsqrtf(v + BN_EPS);
    g_coef[coefoff + k] = sc;
    g_coef[coefoff + 64 + k] = be[k] - m * sc;
}

// fold BN2 affine into fp16 table
__global__ void ktaffine() {
    long i = (long)blockIdx.x * 256 + threadIdx.x;
    if (i >= (long)NB2 * 32) return;
    long b = i >> 5;
    int k2 = (int)(i & 31) * 2;
    float v0 = g_T[b * 64 + k2]     * g_coef[128 + k2]     + g_coef[192 + k2];
    float v1 = g_T[b * 64 + k2 + 1] * g_coef[128 + k2 + 1] + g_coef[192 + k2 + 1];
    g_Th[i] = __floats2half2_rn(v0, v1);
}

__global__ void kemh(const float* __restrict__ edge_emb) {
    int i = blockIdx.x * 256 + threadIdx.x;
    if (i >= 100 * 32) return;
    g_emh[i] = __floats2half2_rn(edge_emb[2 * i], edge_emb[2 * i + 1]);
}

// precompute ea = T[bin] * em[ty] (fp16), layer-invariant, 16 thr/edge
__global__ void kea() {
    int idx = blockIdx.x * 256 + threadIdx.x;
    int e = idx >> 4;
    if (e >= EE) return;
    int l = idx & 15;
    int bt = __ldg(&g_bt[e]);
    int ty = bt & 127;
    long b = bt >> 7;

    uint2 tr = __ldg((const uint2*)&g_Th[b * 32 + l * 2]);
    uint2 er = __ldg((const uint2*)&g_emh[ty * 32 + l * 2]);
    float2 t0 = __half22float2(*(const __half2*)&tr.x);
    float2 t1 = __half22float2(*(const __half2*)&tr.y);
    float2 e0 = __half22float2(*(const __half2*)&er.x);
    float2 e1 = __half22float2(*(const __half2*)&er.y);
    uint2 out;
    *(__half2*)&out.x = __floats2half2_rn(t0.x * e0.x, t0.y * e0.y);
    *(__half2*)&out.y = __floats2half2_rn(t1.x * e1.x, t1.y * e1.y);
    *(uint2*)&g_ea[(long)e * 32 + l * 2] = out;
}

__global__ void kinith(const int* __restrict__ node_type, const float* __restrict__ node_emb) {
    int i = blockIdx.x * 256 + threadIdx.x;
    int n = i >> 6, k = i & 63;
    float v = node_emb[node_type[n] * 64 + k];
    g_h[i] = v;
    g_agg[i] = v;
}

// ---------------- gconv: per-edge, 16 thr/edge, 2 edges/thread ----------------
__global__ void kedge() {
    int idx = blockIdx.x * 256 + threadIdx.x;
    int e = idx >> 4;
    if (e >= HALF) return;
    int l = idx & 15;
    int f0 = l * 4;

    unsigned wa = (unsigned)__ldg(&g_sd[e]);
    unsigned wb = (unsigned)__ldg(&g_sd[e + HALF]);
    int sa = wa & 0xffffu, da = wa >> 16;
    int sb = wb & 0xffffu, db = wb >> 16;

    uint2 eca = __ldg((const uint2*)&g_ea[(long)e * 32 + l * 2]);
    uint2 ecb = __ldg((const uint2*)&g_ea[(long)(e + HALF) * 32 + l * 2]);
    float4 ha = *(const float4*)&g_h[sa * 64 + f0];
    float4 hb = *(const float4*)&g_h[sb * 64 + f0];

    float2 a01 = __half22float2(*(const __half2*)&eca.x);
    float2 a23 = __half22float2(*(const __half2*)&eca.y);
    float2 b01 = __half22float2(*(const __half2*)&ecb.x);
    float2 b23 = __half22float2(*(const __half2*)&ecb.y);

    float a0 = sp(ha.x + a01.x);
    float a1 = sp(ha.y + a01.y);
    float a2 = sp(ha.z + a23.x);
    float a3 = sp(ha.w + a23.y);
    float b0 = sp(hb.x + b01.x);
    float b1 = sp(hb.y + b01.y);
    float b2 = sp(hb.z + b23.x);
    float b3 = sp(hb.w + b23.y);

    float* oa = &g_agg[da * 64 + f0];
    float* ob = &g_agg[db * 64 + f0];
    asm volatile("red.global.add.v4.f32 [%0], {%1, %2, %3, %4};"
                 :: "l"(oa), "f"(a0), "f"(a1), "f"(a2), "f"(a3) : "memory");
    asm volatile("red.global.add.v4.f32 [%0], {%1, %2, %3, %4};"
                 :: "l"(ob), "f"(b0), "f"(b1), "f"(b2), "f"(b3) : "memory");
}

__global__ void knstat(int redoff) {
    int t = threadIdx.x;
    int f0 = (t & 15) * 4;
    float4 s = {0, 0, 0, 0}, q = {0, 0, 0, 0};
    for (int n = blockIdx.x * 16 + (t >> 4); n < NN; n += gridDim.x * 16) {
        float4 v = *(const float4*)&g_agg[n * 64 + f0];
        s.x += v.x; s.y += v.y; s.z += v.z; s.w += v.w;
        q.x += v.x * v.x; q.y += v.y * v.y; q.z += v.z * v.z; q.w += v.w * v.w;
    }
    __shared__ float ssum[64], ssq[64];
    if (t < 64) { ssum[t] = 0.f; ssq[t] = 0.f; }
    __syncthreads();
    atomicAdd(&ssum[f0 + 0], s.x); atomicAdd(&ssum[f0 + 1], s.y);
    atomicAdd(&ssum[f0 + 2], s.z); atomicAdd(&ssum[f0 + 3], s.w);
    atomicAdd(&ssq[f0 + 0], q.x); atomicAdd(&ssq[f0 + 1], q.y);
    atomicAdd(&ssq[f0 + 2], q.z); atomicAdd(&ssq[f0 + 3], q.w);
    __syncthreads();
    if (t < 64) {
        int r = blockIdx.x & 31;
        atomicAdd(&g_red[redoff + r * 128 + t], ssum[t]);
        atomicAdd(&g_red[redoff + r * 128 + 64 + t], ssq[t]);
    }
}

__global__ void kapply(int coefoff, int doact, int dohg, const int* __restrict__ batch) {
    int i = blockIdx.x * 256 + threadIdx.x;
    int n = i >> 4;
    int f0 = (i & 15) * 4;
    float4 v  = *(const float4*)&g_agg[n * 64 + f0];
    float4 sc = *(const float4*)&g_coef[coefoff + f0];
    float4 sh = *(const float4*)&g_coef[coefoff + 64 + f0];
    v.x = v.x * sc.x + sh.x; v.y = v.y * sc.y + sh.y;
    v.z = v.z * sc.z + sh.z; v.w = v.w * sc.w + sh.w;
    if (doact) { v.x = sp(v.x); v.y = sp(v.y); v.z = sp(v.z); v.w = sp(v.w); }
    *(float4*)&g_h[n * 64 + f0] = v;
    *(float4*)&g_agg[n * 64 + f0] = v;   // re-init accumulator for next layer
    if (dohg) {
        int b = batch[n];
        float* o = &g_hg[b * 64 + f0];
        asm volatile("red.global.add.v4.f32 [%0], {%1, %2, %3, %4};"
                     :: "l"(o), "f"(v.x), "f"(v.y), "f"(v.z), "f"(v.w) : "memory");
    }
}

__global__ void kstage1(const int* __restrict__ batch, const float* __restrict__ w_o1,
                        const float* __restrict__ b_o1) {
    __shared__ float snf[4][128];
    __shared__ float ssum[64], ssq[64];
    int t = threadIdx.x, q = t >> 6, k = t & 63;
    int n = blockIdx.x * 4 + q;
    snf[q][k]      = g_h[n * 64 + k];
    snf[q][64 + k] = g_hg[batch[n] * 64 + k];
    if (t < 64) { ssum[t] = 0.f; ssq[t] = 0.f; }
    __syncthreads();
    float acc = b_o1[k];
#pragma unroll
    for (int j4 = 0; j4 < 32; j4++) {
        float4 w4 = __ldg((const float4*)&w_o1[k * 128 + j4 * 4]);
        float4 v = *(const float4*)&snf[q][j4 * 4];
        acc += v.x * w4.x + v.y * w4.y + v.z * w4.z + v.w * w4.w;
    }
    g_y1[n * 64 + k] = acc;
    atomicAdd(&ssum[k], acc);
    atomicAdd(&ssq[k], acc * acc);
    __syncthreads();
    if (t < 64) {
        int r = blockIdx.x & 31;
        atomicAdd(&g_red[OFF_O1 + r * 128 + t], ssum[t]);
        atomicAdd(&g_red[OFF_O1 + r * 128 + 64 + t], ssq[t]);
    }
}

__global__ void kstage2(const float* __restrict__ w_o2, const float* __restrict__ b_o2) {
    __shared__ float sv[4][64];
    __shared__ float ssum[32], ssq[32];
    int t = threadIdx.x, q = t >> 5, k = t & 31;
    int n = blockIdx.x * 4 + q;
    {
        float a = g_y1[n * 64 + k]      * g_coef[640 + k]      + g_coef[704 + k];
        float b = g_y1[n * 64 + 32 + k] * g_coef[640 + 32 + k] + g_coef[704 + 32 + k];
        sv[q][k] = sp(a);
        sv[q][32 + k] = sp(b);
    }
    if (t < 32) { ssum[t] = 0.f; ssq[t] = 0.f; }
    __syncthreads();
    float acc = b_o2[k];
#pragma unroll
    for (int j4 = 0; j4 < 16; j4++) {
        float4 w4 = __ldg((const float4*)&w_o2[k * 64 + j4 * 4]);
        float4 v = *(const float4*)&sv[q][j4 * 4];
        acc += v.x * w4.x + v.y * w4.y + v.z * w4.z + v.w * w4.w;
    }
    g_y2[n * 32 + k] = acc;
    atomicAdd(&ssum[k], acc);
    atomicAdd(&ssq[k], acc * acc);
    __syncthreads();
    if (t < 32) {
        int r = blockIdx.x & 31;
        atomicAdd(&g_red[OFF_O2 + r * 64 + t], ssum[t]);
        atomicAdd(&g_red[OFF_O2 + r * 64 + 32 + t], ssq[t]);
    }
}

__global__ void kstage3(const float* __restrict__ w_o3, const float* __restrict__ b_o3,
                        float* __restrict__ out) {
    __shared__ float sv[2][32];
    int t = threadIdx.x;
    int n2 = blockIdx.x * 2;
    if (t < 64) {
        int q = t >> 5, k = t & 31;
        float a = g_y2[(n2 + q) * 32 + k] * g_coef[768 + k] + g_coef[832 + k];
        sv[q][k] = sp(a);
    }
    __syncthreads();
    int q = t >> 7, c = t & 127;
    int n = n2 + q;
    float acc = b_o3[c];
#pragma unroll
    for (int j4 = 0; j4 < 8; j4++) {
        float4 w4 = __ldg((const float4*)&w_o3[c * 32 + j4 * 4]);
        float4 v = *(const float4*)&sv[q][j4 * 4];
        acc += v.x * w4.x + v.y * w4.y + v.z * w4.z + v.w * w4.w;
    }
    if (c < 64) out[(long)n * 64 + c] = acc;
    else        out[(long)NN * 64 + (long)n * 64 + (c - 64)] = acc;
}

// ---------------- launch ----------------
extern "C" void kernel_launch(void* const* d_in, const int* in_sizes, int n_in,
                              void* d_out, int out_size) {
    const float* x         = (const float*)d_in[0];
    const int*   node_type = (const int*)d_in[1];
    const int*   edge_type = (const int*)d_in[2];
    const int*   edge_index= (const int*)d_in[3];
    const int*   batch     = (const int*)d_in[4];
    const float* node_emb  = (const float*)d_in[5];
    const float* edge_emb  = (const float*)d_in[6];
    const float* w_d1      = (const float*)d_in[7];
    const float* g_d1      = (const float*)d_in[9];
    const float* be_d1     = (const float*)d_in[10];
    const float* w_d2      = (const float*)d_in[11];
    const float* g_d2      = (const float*)d_in[13];
    const float* be_d2     = (const float*)d_in[14];
    const float* g_c1      = (const float*)d_in[15];
    const float* be_c1     = (const float*)d_in[16];
    const float* g_c2      = (const float*)d_in[17];
    const float* be_c2     = (const float*)d_in[18];
    const float* g_c3      = (const float*)d_in[19];
    const float* be_c3     = (const float*)d_in[20];
    const float* w_o1      = (const float*)d_in[21];
    const float* b_o1      = (const float*)d_in[22];
    const float* g_o1      = (const float*)d_in[23];
    const float* be_o1     = (const float*)d_in[24];
    const float* w_o2      = (const float*)d_in[25];
    const float* b_o2      = (const float*)d_in[26];
    const float* g_o2      = (const float*)d_in[27];
    const float* be_o2     = (const float*)d_in[28];
    const float* w_o3      = (const float*)d_in[29];
    const float* b_o3      = (const float*)d_in[30];

    kzero<<<128, 256>>>();
    kprep<<<(EE + 255) / 256, 256>>>(edge_index, edge_type, x);
    kfin_d1<<<1, 64>>>(w_d1, g_d1, be_d1);
    ktable<<<NB2 / 64, 256>>>(w_d2);
    kd2stat<<<NB2 / 64, 64>>>();
    kfinbn<<<1, 64>>>(OFF_D2, 64, (float)EE, g_d2, be_d2, 128);
    ktaffine<<<(int)(((long)NB2 * 32 + 255) / 256), 256>>>();
    kemh<<<13, 256>>>(edge_emb);
    kea<<<(EE * 16 + 255) / 256, 256>>>();
    kinith<<<12500, 256>>>(node_type, node_emb);

    const int   statoff[3] = {OFF_C1, OFF_C2, OFF_C3};
    const int   coefoff[3] = {256, 384, 512};
    const float* gs[3]  = {g_c1, g_c2, g_c3};
    const float* bes[3] = {be_c1, be_c2, be_c3};
    for (int l = 0; l < 3; l++) {
        kedge<<<(HALF * 16 + 255) / 256, 256>>>();
        knstat<<<256, 256>>>(statoff[l]);
        kfinbn<<<1, 64>>>(statoff[l], 64, (float)NN, gs[l], bes[l], coefoff[l]);
        kapply<<<3125, 256>>>(coefoff[l], (l < 2) ? 1 : 0, (l == 2) ? 1 : 0, batch);
    }

    kstage1<<<12500, 256>>>(batch, w_o1, b_o1);
    kfinbn<<<1, 64>>>(OFF_O1, 64, (float)NN, g_o1, be_o1, 640);
    kstage2<<<12500, 128>>>(w_o2, b_o2);
    kfinbn<<<1, 64>>>(OFF_O2, 32, (float)NN, g_o2, be_o2, 768);
    kstage3<<<25000, 256>>>(w_o3, b_o3, (float*)d_out);
}

// round 9
// speedup vs baseline: 1.4969x; 1.4969x over previous
#include <cuda_runtime.h>
#include <cuda_fp16.h>

#define NN 50000
#define EE 1250000
#define QTR 312500
#define HH 64
#define BB 500
#define BN_EPS 1e-5f

#define NB2 32768
#define XLO (-8.0f)
#define INVH2 2048.0f          // NB2/16
#define H2 4.8828125e-4f       // 16/NB2

// ---------------- device scratch ----------------
__device__ float   g_T[(long)NB2 * HH];    // 8MB fp32 table (pre-affine, for stats)
__device__ __half2 g_Th[(long)NB2 * 32];   // 4MB fp16 table, BN2 affine folded
__device__ __half2 g_emh[100 * 32];        // fp16 edge_emb
__device__ int2    g_rec[EE];              // src|dst<<16, ty|bin<<7
__device__ int     g_cnt[NB2];
__device__ float   g_h[NN * HH];
__device__ float   g_agg[NN * HH];
__device__ float   g_hg[BB * HH];
__device__ float   g_y1[NN * 64];
__device__ float   g_y2[NN * 32];
__device__ float   g_red[22592];
__device__ float   g_coef[1024];

#define OFF_X   0
#define OFF_D2  64
#define OFF_C1  4160
#define OFF_C2  8256
#define OFF_C3  12352
#define OFF_O1  16448
#define OFF_O2  20544

__device__ __forceinline__ float sp(float x) {
    float t, l;
    asm("ex2.approx.ftz.f32 %0, %1;" : "=f"(t) : "f"(x * 1.44269504f));
    asm("lg2.approx.f32 %0, %1;" : "=f"(l) : "f"(1.0f + t));
    float r = l * 0.69314718f;
    return x > 20.0f ? x : r;
}

// ---------------- setup kernels ----------------

__global__ void kzero() {
    int i = blockIdx.x * 256 + threadIdx.x;
    if (i < 22592) g_red[i] = 0.0f;
    if (i < BB * HH) g_hg[i] = 0.0f;
    if (i < NB2) g_cnt[i] = 0;
}

// one pass over edges: pack record, count bin, x stats
__global__ void kprep(const int* __restrict__ ei, const int* __restrict__ et,
                      const float* __restrict__ x) {
    int e = blockIdx.x * 256 + threadIdx.x;
    float sx = 0.f, sxx = 0.f;
    if (e < EE) {
        float xv = x[e];
        sx = xv; sxx = xv * xv;
        float u = (xv - XLO) * INVH2;
        int b = (int)u;
        b = max(0, min(NB2 - 1, b));
        atomicAdd(&g_cnt[b], 1);
        g_rec[e] = make_int2(ei[e] | (ei[EE + e] << 16), et[e] | (b << 7));
    }
    __shared__ float ss[256], sq[256];
    int t = threadIdx.x;
    ss[t] = sx; sq[t] = sxx;
    __syncthreads();
    for (int o = 128; o > 0; o >>= 1) {
        if (t < o) { ss[t] += ss[t + o]; sq[t] += sq[t + o]; }
        __syncthreads();
    }
    if (t == 0) {
        int r = blockIdx.x & 31;
        atomicAdd(&g_red[OFF_X + 2 * r], ss[0]);
        atomicAdd(&g_red[OFF_X + 2 * r + 1], sq[0]);
    }
}

__global__ void kfin_d1(const float* __restrict__ w_d1, const float* __restrict__ g_d1,
                        const float* __restrict__ be_d1) {
    __shared__ float S[2];
    if (threadIdx.x == 0) {
        float s = 0.f, q = 0.f;
        for (int r = 0; r < 32; r++) { s += g_red[2 * r]; q += g_red[2 * r + 1]; }
        S[0] = s; S[1] = q;
    }
    __syncthreads();
    float mx = S[0] / (float)EE;
    float vx = S[1] / (float)EE - mx * mx;
    int h = threadIdx.x;
    float w = w_d1[h];
    float a = w * rsqrtf(vx * w * w + BN_EPS) * g_d1[h];
    g_coef[h] = a;
    g_coef[64 + h] = -mx * a + be_d1[h];
}

// table build: tiled GEMM, block = 64 bins x 64 k
__global__ void ktable(const float* __restrict__ w_d2) {
    __shared__ float w2s[64 * 68];
    __shared__ float spv[64 * 64];
    int t = threadIdx.x;
    int j0 = blockIdx.x * 64;

    for (int i = t * 4; i < 4096; i += 1024) {
        float4 v = __ldg((const float4*)&w_d2[i]);
        int k = i >> 6, f = i & 63;
        *(float4*)&w2s[k * 68 + f] = v;
    }
    {
        int f = t & 63;
        float a = g_coef[f], c = g_coef[64 + f];
        for (int j = t >> 6; j < 64; j += 4) {
            float xj = XLO + ((float)(j0 + j) + 0.5f) * H2;
            spv[j * 64 + f] = sp(a * xj + c);
        }
    }
    __syncthreads();

    int k = t & 63;
    int jg = (t >> 6) * 16;
    float acc[16];
#pragma unroll
    for (int i = 0; i < 16; i++) acc[i] = 0.f;
    for (int f4 = 0; f4 < 64; f4 += 4) {
        float4 w4 = *(const float4*)&w2s[k * 68 + f4];
#pragma unroll
        for (int i = 0; i < 16; i++) {
            float4 d = *(const float4*)&spv[(jg + i) * 64 + f4];
            acc[i] += d.x * w4.x + d.y * w4.y + d.z * w4.z + d.w * w4.w;
        }
    }
#pragma unroll
    for (int i = 0; i < 16; i++)
        g_T[(long)(j0 + jg + i) * 64 + k] = acc[i];
}

// BN2 stats from counts (exact for nearest-neighbor quantized d2)
__global__ void kd2stat() {
    int k = threadIdx.x;
    int b0 = blockIdx.x * 64;
    float s = 0.f, q = 0.f;
    for (int j = 0; j < 64; j++) {
        float c = (float)g_cnt[b0 + j];
        float tv = g_T[(long)(b0 + j) * 64 + k];
        s += c * tv;
        q += c * tv * tv;
    }
    int r = blockIdx.x & 31;
    atomicAdd(&g_red[OFF_D2 + r * 128 + k], s);
    atomicAdd(&g_red[OFF_D2 + r * 128 + 64 + k], q);
}

__global__ void kfinbn(int redoff, int F, float cnt, const float* __restrict__ g,
                       const float* __restrict__ be, int coefoff) {
    int k = threadIdx.x;
    if (k >= F) return;
    float s = 0.f, q = 0.f;
    for (int r = 0; r < 32; r++) {
        s += g_red[redoff + r * 2 * F + k];
        q += g_red[redoff + r * 2 * F + F + k];
    }
    float m = s / cnt;
    float v = q / cnt - m * m;
    float sc = g[k] * rsqrtf(v + BN_EPS);
    g_coef[coefoff + k] = sc;
    g_coef[coefoff + 64 + k] = be[k] - m * sc;
}

// fold BN2 affine into fp16 table
__global__ void ktaffine() {
    long i = (long)blockIdx.x * 256 + threadIdx.x;
    if (i >= (long)NB2 * 32) return;
    long b = i >> 5;
    int k2 = (int)(i & 31) * 2;
    float v0 = g_T[b * 64 + k2]     * g_coef[128 + k2]     + g_coef[192 + k2];
    float v1 = g_T[b * 64 + k2 + 1] * g_coef[128 + k2 + 1] + g_coef[192 + k2 + 1];
    g_Th[i] = __floats2half2_rn(v0, v1);
}

__global__ void kemh(const float* __restrict__ edge_emb) {
    int i = blockIdx.x * 256 + threadIdx.x;
    if (i >= 100 * 32) return;
    g_emh[i] = __floats2half2_rn(edge_emb[2 * i], edge_emb[2 * i + 1]);
}

__global__ void kinith(const int* __restrict__ node_type, const float* __restrict__ node_emb) {
    int i = blockIdx.x * 256 + threadIdx.x;
    int n = i >> 6, k = i & 63;
    float v = node_emb[node_type[n] * 64 + k];
    g_h[i] = v;
    g_agg[i] = v;
}

// ---------------- gconv: per-edge, 16 thr/edge, 4 edges/thread ----------------
__global__ void kedge() {
    int idx = blockIdx.x * 256 + threadIdx.x;
    int e = idx >> 4;
    if (e >= QTR) return;
    int l = idx & 15;
    int f0 = l * 4;

    int2 r0 = __ldg(&g_rec[e]);
    int2 r1 = __ldg(&g_rec[e + QTR]);
    int2 r2 = __ldg(&g_rec[e + 2 * QTR]);
    int2 r3 = __ldg(&g_rec[e + 3 * QTR]);

    unsigned w0 = (unsigned)r0.x, w1 = (unsigned)r1.x;
    unsigned w2 = (unsigned)r2.x, w3 = (unsigned)r3.x;
    int s0 = w0 & 0xffffu, d0 = w0 >> 16;
    int s1 = w1 & 0xffffu, d1 = w1 >> 16;
    int s2 = w2 & 0xffffu, d2 = w2 >> 16;
    int s3 = w3 & 0xffffu, d3 = w3 >> 16;

    uint2 t0 = __ldg((const uint2*)&g_Th[(long)(r0.y >> 7) * 32 + l * 2]);
    uint2 t1 = __ldg((const uint2*)&g_Th[(long)(r1.y >> 7) * 32 + l * 2]);
    uint2 t2 = __ldg((const uint2*)&g_Th[(long)(r2.y >> 7) * 32 + l * 2]);
    uint2 t3 = __ldg((const uint2*)&g_Th[(long)(r3.y >> 7) * 32 + l * 2]);
    uint2 e0 = __ldg((const uint2*)&g_emh[(r0.y & 127) * 32 + l * 2]);
    uint2 e1 = __ldg((const uint2*)&g_emh[(r1.y & 127) * 32 + l * 2]);
    uint2 e2 = __ldg((const uint2*)&g_emh[(r2.y & 127) * 32 + l * 2]);
    uint2 e3 = __ldg((const uint2*)&g_emh[(r3.y & 127) * 32 + l * 2]);
    float4 h0 = *(const float4*)&g_h[s0 * 64 + f0];
    float4 h1 = *(const float4*)&g_h[s1 * 64 + f0];
    float4 h2 = *(const float4*)&g_h[s2 * 64 + f0];
    float4 h3 = *(const float4*)&g_h[s3 * 64 + f0];

#define EDGE_MSG(tt, ee, hh, m0, m1, m2, m3)                          \
    {                                                                 \
        float2 ta = __half22float2(*(const __half2*)&tt.x);           \
        float2 tb = __half22float2(*(const __half2*)&tt.y);           \
        float2 ua = __half22float2(*(const __half2*)&ee.x);           \
        float2 ub = __half22float2(*(const __half2*)&ee.y);           \
        m0 = sp(hh.x + ta.x * ua.x);                                  \
        m1 = sp(hh.y + ta.y * ua.y);                                  \
        m2 = sp(hh.z + tb.x * ub.x);                                  \
        m3 = sp(hh.w + tb.y * ub.y);                                  \
    }

    float a0, a1, a2, a3, b0, b1, b2, b3, c0, c1, c2, c3, p0, p1, p2, p3;
    EDGE_MSG(t0, e0, h0, a0, a1, a2, a3)
    EDGE_MSG(t1, e1, h1, b0, b1, b2, b3)
    EDGE_MSG(t2, e2, h2, c0, c1, c2, c3)
    EDGE_MSG(t3, e3, h3, p0, p1, p2, p3)
#undef EDGE_MSG

    asm volatile("red.global.add.v4.f32 [%0], {%1, %2, %3, %4};"
                 :: "l"(&g_agg[d0 * 64 + f0]), "f"(a0), "f"(a1), "f"(a2), "f"(a3) : "memory");
    asm volatile("red.global.add.v4.f32 [%0], {%1, %2, %3, %4};"
                 :: "l"(&g_agg[d1 * 64 + f0]), "f"(b0), "f"(b1), "f"(b2), "f"(b3) : "memory");
    asm volatile("red.global.add.v4.f32 [%0], {%1, %2, %3, %4};"
                 :: "l"(&g_agg[d2 * 64 + f0]), "f"(c0), "f"(c1), "f"(c2), "f"(c3) : "memory");
    asm volatile("red.global.add.v4.f32 [%0], {%1, %2, %3, %4};"
                 :: "l"(&g_agg[d3 * 64 + f0]), "f"(p0), "f"(p1), "f"(p2), "f"(p3) : "memory");
}

__global__ void knstat(int redoff) {
    int t = threadIdx.x;
    int f0 = (t & 15) * 4;
    float4 s = {0, 0, 0, 0}, q = {0, 0, 0, 0};
    for (int n = blockIdx.x * 16 + (t >> 4); n < NN; n += gridDim.x * 16) {
        float4 v = *(const float4*)&g_agg[n * 64 + f0];
        s.x += v.x; s.y += v.y; s.z += v.z; s.w += v.w;
        q.x += v.x * v.x; q.y += v.y * v.y; q.z += v.z * v.z; q.w += v.w * v.w;
    }
    __shared__ float ssum[64], ssq[64];
    if (t < 64) { ssum[t] = 0.f; ssq[t] = 0.f; }
    __syncthreads();
    atomicAdd(&ssum[f0 + 0], s.x); atomicAdd(&ssum[f0 + 1], s.y);
    atomicAdd(&ssum[f0 + 2], s.z); atomicAdd(&ssum[f0 + 3], s.w);
    atomicAdd(&ssq[f0 + 0], q.x); atomicAdd(&ssq[f0 + 1], q.y);
    atomicAdd(&ssq[f0 + 2], q.z); atomicAdd(&ssq[f0 + 3], q.w);
    __syncthreads();
    if (t < 64) {
        int r = blockIdx.x & 31;
        atomicAdd(&g_red[redoff + r * 128 + t], ssum[t]);
        atomicAdd(&g_red[redoff + r * 128 + 64 + t], ssq[t]);
    }
}

__global__ void kapply(int coefoff, int doact, int dohg, const int* __restrict__ batch) {
    int i = blockIdx.x * 256 + threadIdx.x;
    int n = i >> 4;
    int f0 = (i & 15) * 4;
    float4 v  = *(const float4*)&g_agg[n * 64 + f0];
    float4 sc = *(const float4*)&g_coef[coefoff + f0];
    float4 sh = *(const float4*)&g_coef[coefoff + 64 + f0];
    v.x = v.x * sc.x + sh.x; v.y = v.y * sc.y + sh.y;
    v.z = v.z * sc.z + sh.z; v.w = v.w * sc.w + sh.w;
    if (doact) { v.x = sp(v.x); v.y = sp(v.y); v.z = sp(v.z); v.w = sp(v.w); }
    *(float4*)&g_h[n * 64 + f0] = v;
    *(float4*)&g_agg[n * 64 + f0] = v;   // re-init accumulator for next layer
    if (dohg) {
        int b = batch[n];
        float* o = &g_hg[b * 64 + f0];
        asm volatile("red.global.add.v4.f32 [%0], {%1, %2, %3, %4};"
                     :: "l"(o), "f"(v.x), "f"(v.y), "f"(v.z), "f"(v.w) : "memory");
    }
}

// out MLP stage 1: 16 nodes per block (amortize w_o1 refetch)
__global__ void kstage1(const int* __restrict__ batch, const float* __restrict__ w_o1,
                        const float* __restrict__ b_o1) {
    __shared__ float snf[4][128];
    __shared__ float ssum[64], ssq[64];
    int t = threadIdx.x, q = t >> 6, k = t & 63;
    float asum = 0.f, asq = 0.f;
    float bias = b_o1[k];
#pragma unroll 1
    for (int it = 0; it < 4; it++) {
        int n = blockIdx.x * 16 + it * 4 + q;
        __syncthreads();
        snf[q][k]      = g_h[n * 64 + k];
        snf[q][64 + k] = g_hg[batch[n] * 64 + k];
        __syncthreads();
        float acc = bias;
#pragma unroll
        for (int j4 = 0; j4 < 32; j4++) {
            float4 w4 = __ldg((const float4*)&w_o1[k * 128 + j4 * 4]);
            float4 v = *(const float4*)&snf[q][j4 * 4];
            acc += v.x * w4.x + v.y * w4.y + v.z * w4.z + v.w * w4.w;
        }
        g_y1[n * 64 + k] = acc;
        asum += acc; asq += acc * acc;
    }
    if (t < 64) { ssum[t] = 0.f; ssq[t] = 0.f; }
    __syncthreads();
    atomicAdd(&ssum[k], asum);
    atomicAdd(&ssq[k], asq);
    __syncthreads();
    if (t < 64) {
        int r = blockIdx.x & 31;
        atomicAdd(&g_red[OFF_O1 + r * 128 + t], ssum[t]);
        atomicAdd(&g_red[OFF_O1 + r * 128 + 64 + t], ssq[t]);
    }
}

// stage 2: 16 nodes per block
__global__ void kstage2(const float* __restrict__ w_o2, const float* __restrict__ b_o2) {
    __shared__ float sv[4][64];
    __shared__ float ssum[32], ssq[32];
    int t = threadIdx.x, q = t >> 5, k = t & 31;
    float asum = 0.f, asq = 0.f;
    float bias = b_o2[k];
#pragma unroll 1
    for (int it = 0; it < 4; it++) {
        int n = blockIdx.x * 16 + it * 4 + q;
        __syncthreads();
        {
            float a = g_y1[n * 64 + k]      * g_coef[640 + k]      + g_coef[704 + k];
            float b = g_y1[n * 64 + 32 + k] * g_coef[640 + 32 + k] + g_coef[704 + 32 + k];
            sv[q][k] = sp(a);
            sv[q][32 + k] = sp(b);
        }
        __syncthreads();
        float acc = bias;
#pragma unroll
        for (int j4 = 0; j4 < 16; j4++) {
            float4 w4 = __ldg((const float4*)&w_o2[k * 64 + j4 * 4]);
            float4 v = *(const float4*)&sv[q][j4 * 4];
            acc += v.x * w4.x + v.y * w4.y + v.z * w4.z + v.w * w4.w;
        }
        g_y2[n * 32 + k] = acc;
        asum += acc; asq += acc * acc;
    }
    if (t < 32) { ssum[t] = 0.f; ssq[t] = 0.f; }
    __syncthreads();
    atomicAdd(&ssum[k], asum);
    atomicAdd(&ssq[k], asq);
    __syncthreads();
    if (t < 32) {
        int r = blockIdx.x & 31;
        atomicAdd(&g_red[OFF_O2 + r * 64 + t], ssum[t]);
        atomicAdd(&g_red[OFF_O2 + r * 64 + 32 + t], ssq[t]);
    }
}

// stage 3: 16 nodes per block (8 iterations of 2)
__global__ void kstage3(const float* __restrict__ w_o3, const float* __restrict__ b_o3,
                        float* __restrict__ out) {
    __shared__ float sv[2][32];
    int t = threadIdx.x;
    int q = t >> 7, c = t & 127;
    float bias = b_o3[c];
#pragma unroll 1
    for (int it = 0; it < 8; it++) {
        int n2 = blockIdx.x * 16 + it * 2;
        __syncthreads();
        if (t < 64) {
            int qq = t >> 5, k = t & 31;
            float a = g_y2[(n2 + qq) * 32 + k] * g_coef[768 + k] + g_coef[832 + k];
            sv[qq][k] = sp(a);
        }
        __syncthreads();
        int n = n2 + q;
        float acc = bias;
#pragma unroll
        for (int j4 = 0; j4 < 8; j4++) {
            float4 w4 = __ldg((const float4*)&w_o3[c * 32 + j4 * 4]);
            float4 v = *(const float4*)&sv[q][j4 * 4];
            acc += v.x * w4.x + v.y * w4.y + v.z * w4.z + v.w * w4.w;
        }
        if (c < 64) out[(long)n * 64 + c] = acc;
        else        out[(long)NN * 64 + (long)n * 64 + (c - 64)] = acc;
    }
}

// ---------------- launch ----------------
extern "C" void kernel_launch(void* const* d_in, const int* in_sizes, int n_in,
                              void* d_out, int out_size) {
    const float* x         = (const float*)d_in[0];
    const int*   node_type = (const int*)d_in[1];
    const int*   edge_type = (const int*)d_in[2];
    const int*   edge_index= (const int*)d_in[3];
    const int*   batch     = (const int*)d_in[4];
    const float* node_emb  = (const float*)d_in[5];
    const float* edge_emb  = (const float*)d_in[6];
    const float* w_d1      = (const float*)d_in[7];
    const float* g_d1      = (const float*)d_in[9];
    const float* be_d1     = (const float*)d_in[10];
    const float* w_d2      = (const float*)d_in[11];
    const float* g_d2      = (const float*)d_in[13];
    const float* be_d2     = (const float*)d_in[14];
    const float* g_c1      = (const float*)d_in[15];
    const float* be_c1     = (const float*)d_in[16];
    const float* g_c2      = (const float*)d_in[17];
    const float* be_c2     = (const float*)d_in[18];
    const float* g_c3      = (const float*)d_in[19];
    const float* be_c3     = (const float*)d_in[20];
    const float* w_o1      = (const float*)d_in[21];
    const float* b_o1      = (const float*)d_in[22];
    const float* g_o1      = (const float*)d_in[23];
    const float* be_o1     = (const float*)d_in[24];
    const float* w_o2      = (const float*)d_in[25];
    const float* b_o2      = (const float*)d_in[26];
    const float* g_o2      = (const float*)d_in[27];
    const float* be_o2     = (const float*)d_in[28];
    const float* w_o3      = (const float*)d_in[29];
    const float* b_o3      = (const float*)d_in[30];

    kzero<<<128, 256>>>();
    kprep<<<(EE + 255) / 256, 256>>>(edge_index, edge_type, x);
    kfin_d1<<<1, 64>>>(w_d1, g_d1, be_d1);
    ktable<<<NB2 / 64, 256>>>(w_d2);
    kd2stat<<<NB2 / 64, 64>>>();
    kfinbn<<<1, 64>>>(OFF_D2, 64, (float)EE, g_d2, be_d2, 128);
    ktaffine<<<(int)(((long)NB2 * 32 + 255) / 256), 256>>>();
    kemh<<<13, 256>>>(edge_emb);
    kinith<<<12500, 256>>>(node_type, node_emb);

    const int   statoff[3] = {OFF_C1, OFF_C2, OFF_C3};
    const int   coefoff[3] = {256, 384, 512};
    const float* gs[3]  = {g_c1, g_c2, g_c3};
    const float* bes[3] = {be_c1, be_c2, be_c3};
    for (int l = 0; l < 3; l++) {
        kedge<<<(QTR * 16 + 255) / 256, 256>>>();
        knstat<<<256, 256>>>(statoff[l]);
        kfinbn<<<1, 64>>>(statoff[l], 64, (float)NN, gs[l], bes[l], coefoff[l]);
        kapply<<<3125, 256>>>(coefoff[l], (l < 2) ? 1 : 0, (l == 2) ? 1 : 0, batch);
    }

    kstage1<<<3125, 256>>>(batch, w_o1, b_o1);
    kfinbn<<<1, 64>>>(OFF_O1, 64, (float)NN, g_o1, be_o1, 640);
    kstage2<<<3125, 128>>>(w_o2, b_o2);
    kfinbn<<<1, 64>>>(OFF_O2, 32, (float)NN, g_o2, be_o2, 768);
    kstage3<<<3125, 256>>>(w_o3, b_o3, (float*)d_out);
}